// round 11
// baseline (speedup 1.0000x reference)
#include <cuda_runtime.h>
#include <cuda_bf16.h>
#include <math_constants.h>

// Problem constants
#define Bc 16
#define Dc 512
#define Hc 64
#define Wc 64
#define Mc 512
#define Nc (Bc*Hc*Wc)      // 65536
#define HWc (Hc*Wc)        // 4096

// d_out layout (tuple order: upd_q, upd_mem, s_query, s_memory, separateness, compactness)
#define OFF_UPDQ   0
#define SZ_UPDQ    (Bc*2*Dc*Hc*Wc)        // 67108864
#define OFF_UPDMEM (OFF_UPDQ + SZ_UPDQ)   // 67108864
#define SZ_UPDMEM  (Mc*Dc)                // 262144
#define OFF_SQ     (OFF_UPDMEM + SZ_UPDMEM) // 67371008
#define SZ_SQ      (Nc*Mc)                // 33554432
#define OFF_SM     (OFF_SQ + SZ_SQ)       // 100925440
#define OFF_SEP    (OFF_SM + SZ_SQ)       // 134479872
#define OFF_COMP   (OFF_SEP + 1)          // 134479873

// Scratch (device globals; no allocation in kernel_launch)
__device__ float g_qr[(size_t)Nc * Dc];        // 134 MB: normalized queries, row-major [N, D]
__device__ float g_keysT[Mc * Dc];             // keys transposed [D, M]
__device__ float g_qupd[Mc * Dc];              // segment-sum accumulator
__device__ float g_pmax[256 * Mc];             // column partial max
__device__ float g_psum[256 * Mc];             // column partial sumexp
__device__ float g_colmax[Mc];
__device__ float g_colinv[Mc];                 // 1/colsum
__device__ float g_scal[2];                    // [0]=compactness sum, [1]=separateness sum

// ---------------------------------------------------------------------------
// K0: zero accumulators (must run every launch — graph replays)
// ---------------------------------------------------------------------------
__global__ void kz() {
    int i = blockIdx.x * 256 + threadIdx.x;
    if (i < Mc * Dc) g_qupd[i] = 0.0f;
    if (i < 2) g_scal[i] = 0.0f;
}

// ---------------------------------------------------------------------------
// K1: per-pixel L2 normalize; write qr [N,D] (coalesced via smem transpose)
//     and upd_q first half (same layout as input query).
// grid 1024 (= b*64+h), 256 threads
// ---------------------------------------------------------------------------
__global__ void __launch_bounds__(256) k1_norm(const float* __restrict__ q,
                                               float* __restrict__ updq) {
    __shared__ float tile[128][65];
    __shared__ float ps[4][64];
    __shared__ float sinv[64];
    int bh = blockIdx.x;
    int b = bh >> 6, h = bh & 63;
    int t = threadIdx.x;
    int w = t & 63, seg = t >> 6;

    const float* qp = q + (size_t)b * (Dc * HWc) + h * Wc + w;
    float acc = 0.0f;
    #pragma unroll 4
    for (int d = seg * 128; d < seg * 128 + 128; d++) {
        float x = qp[(size_t)d * HWc];
        acc += x * x;
    }
    ps[seg][w] = acc;
    __syncthreads();
    if (t < 64) {
        float ss = ps[0][t] + ps[1][t] + ps[2][t] + ps[3][t];
        sinv[t] = 1.0f / fmaxf(sqrtf(ss), 1e-12f);
    }
    __syncthreads();

    size_t qbase = (size_t)b * (Dc * HWc) + h * Wc;
    size_t ubase = (size_t)b * (2 * Dc * HWc) + h * Wc;
    size_t rbase = (size_t)bh * 64;
    for (int dc = 0; dc < 4; dc++) {
        for (int i = t; i < 8192; i += 256) {
            int d = i >> 6, ww = i & 63;
            float x = q[qbase + (size_t)(dc * 128 + d) * HWc + ww];
            tile[d][ww] = x;
            updq[ubase + (size_t)(dc * 128 + d) * HWc + ww] = x * sinv[ww];
        }
        __syncthreads();
        for (int i = t; i < 8192; i += 256) {
            int ww = i >> 7, d = i & 127;
            g_qr[(rbase + ww) * Dc + dc * 128 + d] = tile[d][ww] * sinv[ww];
        }
        __syncthreads();
    }
}

// ---------------------------------------------------------------------------
// K_tr: keysT[d][m] = keys[m][d]
// ---------------------------------------------------------------------------
__global__ void ktr(const float* __restrict__ keys) {
    __shared__ float tl[32][33];
    int x = blockIdx.x * 32 + threadIdx.x;   // d
    int y0 = blockIdx.y * 32;                // m
    for (int i = threadIdx.y; i < 32; i += 8)
        tl[i][threadIdx.x] = keys[(y0 + i) * Dc + x];
    __syncthreads();
    int xo = blockIdx.y * 32 + threadIdx.x;  // m
    int yo = blockIdx.x * 32;                // d
    for (int i = threadIdx.y; i < 32; i += 8)
        g_keysT[(yo + i) * Mc + xo] = tl[threadIdx.x][i];
}

// ---------------------------------------------------------------------------
// SGEMM NT: C[row,col] = sum_k A[row,k]*Bm[col,k], K=512 fixed.
// 128x128 tile, BK=16, 256 threads, 8x8 per-thread (4+4 split).
// EPI=0: C -> out[row*512+col]   (score into s_query region)
// EPI=1: row=d, col=r -> upd_q second half [b, 512+d, h, w]
// ---------------------------------------------------------------------------
#define BK 16
#define SSTRIDE 132   // 128+4, keeps 16B alignment for float4 smem loads

template <int EPI>
__global__ void __launch_bounds__(256) sgemm_nt(const float* __restrict__ A,
                                                const float* __restrict__ Bm,
                                                float* __restrict__ out) {
    __shared__ float As[BK][SSTRIDE];
    __shared__ float Bs[BK][SSTRIDE];
    const int tid = threadIdx.x;
    const int tx = tid & 15, ty = tid >> 4;
    const int arow0 = blockIdx.y * 128;
    const int brow0 = blockIdx.x * 128;
    const int lr = tid >> 2;            // 0..63
    const int lk = (tid & 3) * 4;       // 0,4,8,12

    float acc[8][8];
    #pragma unroll
    for (int i = 0; i < 8; i++)
        #pragma unroll
        for (int j = 0; j < 8; j++) acc[i][j] = 0.0f;

    for (int kt = 0; kt < 512; kt += BK) {
        float4 a0 = *(const float4*)&A[(size_t)(arow0 + lr) * 512 + kt + lk];
        float4 a1 = *(const float4*)&A[(size_t)(arow0 + lr + 64) * 512 + kt + lk];
        float4 b0 = *(const float4*)&Bm[(size_t)(brow0 + lr) * 512 + kt + lk];
        float4 b1 = *(const float4*)&Bm[(size_t)(brow0 + lr + 64) * 512 + kt + lk];
        __syncthreads();
        As[lk + 0][lr] = a0.x; As[lk + 1][lr] = a0.y; As[lk + 2][lr] = a0.z; As[lk + 3][lr] = a0.w;
        As[lk + 0][lr + 64] = a1.x; As[lk + 1][lr + 64] = a1.y; As[lk + 2][lr + 64] = a1.z; As[lk + 3][lr + 64] = a1.w;
        Bs[lk + 0][lr] = b0.x; Bs[lk + 1][lr] = b0.y; Bs[lk + 2][lr] = b0.z; Bs[lk + 3][lr] = b0.w;
        Bs[lk + 0][lr + 64] = b1.x; Bs[lk + 1][lr + 64] = b1.y; Bs[lk + 2][lr + 64] = b1.z; Bs[lk + 3][lr + 64] = b1.w;
        __syncthreads();
        #pragma unroll
        for (int kk = 0; kk < BK; kk++) {
            float4 ra0 = *(const float4*)&As[kk][ty * 4];
            float4 ra1 = *(const float4*)&As[kk][64 + ty * 4];
            float4 rb0 = *(const float4*)&Bs[kk][tx * 4];
            float4 rb1 = *(const float4*)&Bs[kk][64 + tx * 4];
            float a[8] = {ra0.x, ra0.y, ra0.z, ra0.w, ra1.x, ra1.y, ra1.z, ra1.w};
            float bb[8] = {rb0.x, rb0.y, rb0.z, rb0.w, rb1.x, rb1.y, rb1.z, rb1.w};
            #pragma unroll
            for (int i = 0; i < 8; i++)
                #pragma unroll
                for (int j = 0; j < 8; j++) acc[i][j] += a[i] * bb[j];
        }
    }

    #pragma unroll
    for (int hi = 0; hi < 2; hi++) {
        #pragma unroll
        for (int i = 0; i < 4; i++) {
            int row = arow0 + hi * 64 + ty * 4 + i;
            #pragma unroll
            for (int hj = 0; hj < 2; hj++) {
                int col = brow0 + hj * 64 + tx * 4;
                float4 v;
                v.x = acc[hi * 4 + i][hj * 4 + 0];
                v.y = acc[hi * 4 + i][hj * 4 + 1];
                v.z = acc[hi * 4 + i][hj * 4 + 2];
                v.w = acc[hi * 4 + i][hj * 4 + 3];
                if (EPI == 0) {
                    *(float4*)&out[(size_t)row * 512 + col] = v;
                } else {
                    // row = d, col = r = (b*64+h)*64 + w ; w%4==0 so float4 safe
                    int r = col;
                    int bb2 = r >> 12, hh = (r >> 6) & 63, ww = r & 63;
                    size_t idx = (size_t)bb2 * (2 * Dc * HWc) + (size_t)(Dc + row) * HWc + hh * Wc + ww;
                    *(float4*)&out[idx] = v;
                }
            }
        }
    }
}

// ---------------------------------------------------------------------------
// K3a: per-block online column (max, sumexp) over 256 rows. 256 blocks x 512 thr.
// ---------------------------------------------------------------------------
__global__ void __launch_bounds__(512) k3a(const float* __restrict__ raw) {
    int t = threadIdx.x;
    const float* p = raw + (size_t)blockIdx.x * 256 * Mc + t;
    float mx = -CUDART_INF_F, s = 0.0f;
    for (int n = 0; n < 256; n++) {
        float v = p[(size_t)n * Mc];
        if (v > mx) { s = s * __expf(mx - v) + 1.0f; mx = v; }
        else s += __expf(v - mx);
    }
    g_pmax[blockIdx.x * Mc + t] = mx;
    g_psum[blockIdx.x * Mc + t] = s;
}

__global__ void __launch_bounds__(512) k3b() {
    int t = threadIdx.x;
    float mx = g_pmax[t], s = g_psum[t];
    for (int i = 1; i < 256; i++) {
        float m2 = g_pmax[i * Mc + t], s2 = g_psum[i * Mc + t];
        if (m2 > mx) { s = s * __expf(mx - m2) + s2; mx = m2; }
        else s += s2 * __expf(m2 - mx);
    }
    g_colmax[t] = mx;
    g_colinv[t] = 1.0f / s;
}

// ---------------------------------------------------------------------------
// K4: warp per row. Row softmax -> s_memory; s_query in place; top2; wgt;
//     triplet distances; segment-sum atomics.
// grid 8192 x 256 threads (8 warps)
// ---------------------------------------------------------------------------
__global__ void __launch_bounds__(256) k4(float* __restrict__ sq,
                                          float* __restrict__ sm,
                                          const float* __restrict__ keys) {
    const int warp = threadIdx.x >> 5, lane = threadIdx.x & 31;
    const int r = blockIdx.x * 8 + warp;
    const size_t rb = (size_t)r * Mc;

    float v[16];
    #pragma unroll
    for (int k = 0; k < 16; k++) v[k] = sq[rb + lane + (k << 5)];

    // top-2 (value, index), ties -> lower index
    float v1 = -CUDART_INF_F, v2 = -CUDART_INF_F;
    int i1 = 1 << 30, i2 = 1 << 30;
    #pragma unroll
    for (int k = 0; k < 16; k++) {
        float x = v[k]; int idx = lane + (k << 5);
        if (x > v1) { v2 = v1; i2 = i1; v1 = x; i1 = idx; }
        else if (x > v2) { v2 = x; i2 = idx; }
    }
    #pragma unroll
    for (int off = 16; off; off >>= 1) {
        float ov1 = __shfl_down_sync(0xffffffffu, v1, off);
        int   oi1 = __shfl_down_sync(0xffffffffu, i1, off);
        float ov2 = __shfl_down_sync(0xffffffffu, v2, off);
        int   oi2 = __shfl_down_sync(0xffffffffu, i2, off);
        bool og = (ov1 > v1) || (ov1 == v1 && oi1 < i1);
        float w1 = og ? ov1 : v1; int wi1 = og ? oi1 : i1;
        float l1 = og ? v1 : ov1; int li1 = og ? i1 : oi1;
        float ws = og ? ov2 : v2; int wsi = og ? oi2 : i2;
        bool lg = (l1 > ws) || (l1 == ws && li1 < wsi);
        v1 = w1; i1 = wi1;
        v2 = lg ? l1 : ws; i2 = lg ? li1 : wsi;
    }
    v1 = __shfl_sync(0xffffffffu, v1, 0); i1 = __shfl_sync(0xffffffffu, i1, 0);
    i2 = __shfl_sync(0xffffffffu, i2, 0);

    // row softmax
    float es[16], rs = 0.0f;
    #pragma unroll
    for (int k = 0; k < 16; k++) { es[k] = __expf(v[k] - v1); rs += es[k]; }
    #pragma unroll
    for (int off = 16; off; off >>= 1) rs += __shfl_xor_sync(0xffffffffu, rs, off);
    float rinv = 1.0f / rs;

    #pragma unroll
    for (int k = 0; k < 16; k++) {
        int m = lane + (k << 5);
        sm[rb + m] = es[k] * rinv;                                // s_memory
        sq[rb + m] = __expf(v[k] - g_colmax[m]) * g_colinv[m];    // s_query (in place)
    }

    // wgt = (s_query/col_max)[r, top1] = exp(score - colmax)
    float wgt = __expf(v1 - g_colmax[i1]);

    // distances + segment-sum scatter
    float ac = 0.0f, ap = 0.0f, an = 0.0f;
    const float* kp = keys + (size_t)i1 * Dc;
    const float* kn = keys + (size_t)i2 * Dc;
    #pragma unroll
    for (int k = 0; k < 16; k++) {
        int d = lane + (k << 5);
        float qv = g_qr[(size_t)r * Dc + d];
        float pv = kp[d], nv = kn[d];
        float d0 = qv - pv;            ac += d0 * d0;
        float dp = d0 + 1e-6f;         ap += dp * dp;
        float dn = qv - nv + 1e-6f;    an += dn * dn;
        atomicAdd(&g_qupd[i1 * Dc + d], wgt * qv);
    }
    #pragma unroll
    for (int off = 16; off; off >>= 1) {
        ac += __shfl_down_sync(0xffffffffu, ac, off);
        ap += __shfl_down_sync(0xffffffffu, ap, off);
        an += __shfl_down_sync(0xffffffffu, an, off);
    }
    __shared__ float scmp[8], ssep[8];
    if (lane == 0) {
        scmp[warp] = ac;
        ssep[warp] = fmaxf(sqrtf(ap) - sqrtf(an) + 1.0f, 0.0f);
    }
    __syncthreads();
    if (threadIdx.x == 0) {
        float c = 0.0f, s = 0.0f;
        #pragma unroll
        for (int i = 0; i < 8; i++) { c += scmp[i]; s += ssep[i]; }
        atomicAdd(&g_scal[0], c);
        atomicAdd(&g_scal[1], s);
    }
}

// ---------------------------------------------------------------------------
// K7: upd_mem = l2norm(q_update + keys). 512 blocks x 128 threads.
// ---------------------------------------------------------------------------
__global__ void __launch_bounds__(128) k7(const float* __restrict__ keys,
                                          float* __restrict__ updmem) {
    int m = blockIdx.x, t = threadIdx.x;
    float vv[4], ss = 0.0f;
    #pragma unroll
    for (int i = 0; i < 4; i++) {
        int d = t + i * 128;
        vv[i] = g_qupd[m * Dc + d] + keys[m * Dc + d];
        ss += vv[i] * vv[i];
    }
    #pragma unroll
    for (int off = 16; off; off >>= 1) ss += __shfl_xor_sync(0xffffffffu, ss, off);
    __shared__ float sw[4];
    if ((t & 31) == 0) sw[t >> 5] = ss;
    __syncthreads();
    float tot = sw[0] + sw[1] + sw[2] + sw[3];
    float inv = 1.0f / fmaxf(sqrtf(tot), 1e-12f);
    #pragma unroll
    for (int i = 0; i < 4; i++) updmem[m * Dc + t + i * 128] = vv[i] * inv;
}

__global__ void k8(float* __restrict__ o_sep, float* __restrict__ o_comp) {
    *o_sep = g_scal[1] / (float)Nc;
    *o_comp = g_scal[0] / ((float)Nc * (float)Dc);
}

// ---------------------------------------------------------------------------
extern "C" void kernel_launch(void* const* d_in, const int* in_sizes, int n_in,
                              void* d_out, int out_size) {
    const float* query = (const float*)d_in[0];
    const float* keys  = (const float*)d_in[1];
    float* out = (float*)d_out;
    float* o_updq   = out + OFF_UPDQ;
    float* o_updmem = out + OFF_UPDMEM;
    float* o_sq     = out + OFF_SQ;
    float* o_sm     = out + OFF_SM;
    float* o_sep    = out + OFF_SEP;
    float* o_comp   = out + OFF_COMP;

    // CRITICAL FIX: __device__ globals must be resolved to DEVICE addresses
    // before being passed as kernel arguments. Referencing the symbol in host
    // code yields the host-side shadow (readable via ATS on GB300 -> silent
    // zeros, which zeroed the score and concat_mem halves last round).
    float* p_qr = nullptr;
    float* p_keysT = nullptr;
    cudaGetSymbolAddress((void**)&p_qr, g_qr);
    cudaGetSymbolAddress((void**)&p_keysT, g_keysT);

    kz<<<(Mc * Dc + 255) / 256, 256>>>();
    k1_norm<<<Bc * Hc, 256>>>(query, o_updq);
    ktr<<<dim3(16, 16), dim3(32, 8)>>>(keys);

    // score = qr @ keys^T  -> raw scores into s_query region
    sgemm_nt<0><<<dim3(Mc / 128, Nc / 128), 256>>>(p_qr, keys, o_sq);

    k3a<<<256, 512>>>(o_sq);
    k3b<<<1, 512>>>();
    k4<<<Nc / 8, 256>>>(o_sq, o_sm, keys);

    // concat_mem^T = keysT @ s_memory^T -> upd_q second half (coalesced over w)
    sgemm_nt<1><<<dim3(Nc / 128, Dc / 128), 256>>>(p_keysT, o_sm, o_updq);

    k7<<<Mc, 128>>>(keys, o_updmem);
    k8<<<1, 1>>>(o_sep, o_comp);
}

// round 12
// speedup vs baseline: 1.0002x; 1.0002x over previous
#include <cuda_runtime.h>
#include <cuda_bf16.h>
#include <math_constants.h>

// Problem constants
#define Bc 16
#define Dc 512
#define Hc 64
#define Wc 64
#define Mc 512
#define Nc (Bc*Hc*Wc)      // 65536
#define HWc (Hc*Wc)        // 4096

// d_out layout (tuple order: upd_q, upd_mem, s_query, s_memory, separateness, compactness)
#define OFF_UPDQ   0
#define SZ_UPDQ    (Bc*2*Dc*Hc*Wc)        // 67108864
#define OFF_UPDMEM (OFF_UPDQ + SZ_UPDQ)   // 67108864
#define SZ_UPDMEM  (Mc*Dc)                // 262144
#define OFF_SQ     (OFF_UPDMEM + SZ_UPDMEM) // 67371008
#define SZ_SQ      (Nc*Mc)                // 33554432
#define OFF_SM     (OFF_SQ + SZ_SQ)       // 100925440
#define OFF_SEP    (OFF_SM + SZ_SQ)       // 134479872
#define OFF_COMP   (OFF_SEP + 1)          // 134479873

// Scratch (device globals; no allocation in kernel_launch)
__device__ float g_qr[(size_t)Nc * Dc];        // 134 MB: normalized queries, row-major [N, D]
__device__ float g_keysT[Mc * Dc];             // keys transposed [D, M]
__device__ float g_qupd[Mc * Dc];              // segment-sum accumulator
__device__ float g_pmax[256 * Mc];             // column partial max
__device__ float g_psum[256 * Mc];             // column partial sumexp
__device__ float g_colmax[Mc];
__device__ float g_colinv[Mc];                 // 1/colsum
__device__ float g_scal[2];                    // [0]=compactness sum, [1]=separateness sum

// ---------------------------------------------------------------------------
// K0: zero accumulators (must run every launch — graph replays)
// ---------------------------------------------------------------------------
__global__ void kz() {
    int i = blockIdx.x * 256 + threadIdx.x;
    if (i < Mc * Dc) g_qupd[i] = 0.0f;
    if (i < 2) g_scal[i] = 0.0f;
}

// ---------------------------------------------------------------------------
// K1: per-pixel L2 normalize; write qr [N,D] (coalesced via smem transpose)
//     and upd_q first half (same layout as input query).
// grid 1024 (= b*64+h), 256 threads
// ---------------------------------------------------------------------------
__global__ void __launch_bounds__(256) k1_norm(const float* __restrict__ q,
                                               float* __restrict__ updq) {
    __shared__ float tile[128][65];
    __shared__ float ps[4][64];
    __shared__ float sinv[64];
    int bh = blockIdx.x;
    int b = bh >> 6, h = bh & 63;
    int t = threadIdx.x;
    int w = t & 63, seg = t >> 6;

    const float* qp = q + (size_t)b * (Dc * HWc) + h * Wc + w;
    float acc = 0.0f;
    #pragma unroll 4
    for (int d = seg * 128; d < seg * 128 + 128; d++) {
        float x = qp[(size_t)d * HWc];
        acc += x * x;
    }
    ps[seg][w] = acc;
    __syncthreads();
    if (t < 64) {
        float ss = ps[0][t] + ps[1][t] + ps[2][t] + ps[3][t];
        sinv[t] = 1.0f / fmaxf(sqrtf(ss), 1e-12f);
    }
    __syncthreads();

    size_t qbase = (size_t)b * (Dc * HWc) + h * Wc;
    size_t ubase = (size_t)b * (2 * Dc * HWc) + h * Wc;
    size_t rbase = (size_t)bh * 64;
    for (int dc = 0; dc < 4; dc++) {
        for (int i = t; i < 8192; i += 256) {
            int d = i >> 6, ww = i & 63;
            float x = q[qbase + (size_t)(dc * 128 + d) * HWc + ww];
            tile[d][ww] = x;
            updq[ubase + (size_t)(dc * 128 + d) * HWc + ww] = x * sinv[ww];
        }
        __syncthreads();
        for (int i = t; i < 8192; i += 256) {
            int ww = i >> 7, d = i & 127;
            g_qr[(rbase + ww) * Dc + dc * 128 + d] = tile[d][ww] * sinv[ww];
        }
        __syncthreads();
    }
}

// ---------------------------------------------------------------------------
// K_tr: keysT[d][m] = keys[m][d]
// ---------------------------------------------------------------------------
__global__ void ktr(const float* __restrict__ keys) {
    __shared__ float tl[32][33];
    int x = blockIdx.x * 32 + threadIdx.x;   // d
    int y0 = blockIdx.y * 32;                // m
    for (int i = threadIdx.y; i < 32; i += 8)
        tl[i][threadIdx.x] = keys[(y0 + i) * Dc + x];
    __syncthreads();
    int xo = blockIdx.y * 32 + threadIdx.x;  // m
    int yo = blockIdx.x * 32;                // d
    for (int i = threadIdx.y; i < 32; i += 8)
        g_keysT[(yo + i) * Mc + xo] = tl[threadIdx.x][i];
}

// ---------------------------------------------------------------------------
// SGEMM NT: C[row,col] = sum_k A[row,k]*Bm[col,k], K=512 fixed.
// 128x128 tile, BK=16, 256 threads, 8x8 per-thread (4+4 split).
// EPI=0: C -> out[row*512+col]   (score into s_query region)
// EPI=1: row=d, col=r -> upd_q second half [b, 512+d, h, w]
// ---------------------------------------------------------------------------
#define BK 16
#define SSTRIDE 132   // 128+4, keeps 16B alignment for float4 smem loads

template <int EPI>
__global__ void __launch_bounds__(256) sgemm_nt(const float* __restrict__ A,
                                                const float* __restrict__ Bm,
                                                float* __restrict__ out) {
    __shared__ float As[BK][SSTRIDE];
    __shared__ float Bs[BK][SSTRIDE];
    const int tid = threadIdx.x;
    const int tx = tid & 15, ty = tid >> 4;
    const int arow0 = blockIdx.y * 128;
    const int brow0 = blockIdx.x * 128;
    const int lr = tid >> 2;            // 0..63
    const int lk = (tid & 3) * 4;       // 0,4,8,12

    float acc[8][8];
    #pragma unroll
    for (int i = 0; i < 8; i++)
        #pragma unroll
        for (int j = 0; j < 8; j++) acc[i][j] = 0.0f;

    for (int kt = 0; kt < 512; kt += BK) {
        float4 a0 = *(const float4*)&A[(size_t)(arow0 + lr) * 512 + kt + lk];
        float4 a1 = *(const float4*)&A[(size_t)(arow0 + lr + 64) * 512 + kt + lk];
        float4 b0 = *(const float4*)&Bm[(size_t)(brow0 + lr) * 512 + kt + lk];
        float4 b1 = *(const float4*)&Bm[(size_t)(brow0 + lr + 64) * 512 + kt + lk];
        __syncthreads();
        As[lk + 0][lr] = a0.x; As[lk + 1][lr] = a0.y; As[lk + 2][lr] = a0.z; As[lk + 3][lr] = a0.w;
        As[lk + 0][lr + 64] = a1.x; As[lk + 1][lr + 64] = a1.y; As[lk + 2][lr + 64] = a1.z; As[lk + 3][lr + 64] = a1.w;
        Bs[lk + 0][lr] = b0.x; Bs[lk + 1][lr] = b0.y; Bs[lk + 2][lr] = b0.z; Bs[lk + 3][lr] = b0.w;
        Bs[lk + 0][lr + 64] = b1.x; Bs[lk + 1][lr + 64] = b1.y; Bs[lk + 2][lr + 64] = b1.z; Bs[lk + 3][lr + 64] = b1.w;
        __syncthreads();
        #pragma unroll
        for (int kk = 0; kk < BK; kk++) {
            float4 ra0 = *(const float4*)&As[kk][ty * 4];
            float4 ra1 = *(const float4*)&As[kk][64 + ty * 4];
            float4 rb0 = *(const float4*)&Bs[kk][tx * 4];
            float4 rb1 = *(const float4*)&Bs[kk][64 + tx * 4];
            float a[8] = {ra0.x, ra0.y, ra0.z, ra0.w, ra1.x, ra1.y, ra1.z, ra1.w};
            float bb[8] = {rb0.x, rb0.y, rb0.z, rb0.w, rb1.x, rb1.y, rb1.z, rb1.w};
            #pragma unroll
            for (int i = 0; i < 8; i++)
                #pragma unroll
                for (int j = 0; j < 8; j++) acc[i][j] += a[i] * bb[j];
        }
    }

    #pragma unroll
    for (int hi = 0; hi < 2; hi++) {
        #pragma unroll
        for (int i = 0; i < 4; i++) {
            int row = arow0 + hi * 64 + ty * 4 + i;
            #pragma unroll
            for (int hj = 0; hj < 2; hj++) {
                int col = brow0 + hj * 64 + tx * 4;
                float4 v;
                v.x = acc[hi * 4 + i][hj * 4 + 0];
                v.y = acc[hi * 4 + i][hj * 4 + 1];
                v.z = acc[hi * 4 + i][hj * 4 + 2];
                v.w = acc[hi * 4 + i][hj * 4 + 3];
                if (EPI == 0) {
                    *(float4*)&out[(size_t)row * 512 + col] = v;
                } else {
                    // row = d, col = r = (b*64+h)*64 + w ; w%4==0 so float4 safe
                    int r = col;
                    int bb2 = r >> 12, hh = (r >> 6) & 63, ww = r & 63;
                    size_t idx = (size_t)bb2 * (2 * Dc * HWc) + (size_t)(Dc + row) * HWc + hh * Wc + ww;
                    *(float4*)&out[idx] = v;
                }
            }
        }
    }
}

// ---------------------------------------------------------------------------
// K3a: per-block online column (max, sumexp) over 256 rows. 256 blocks x 512 thr.
// ---------------------------------------------------------------------------
__global__ void __launch_bounds__(512) k3a(const float* __restrict__ raw) {
    int t = threadIdx.x;
    const float* p = raw + (size_t)blockIdx.x * 256 * Mc + t;
    float mx = -CUDART_INF_F, s = 0.0f;
    for (int n = 0; n < 256; n++) {
        float v = p[(size_t)n * Mc];
        if (v > mx) { s = s * __expf(mx - v) + 1.0f; mx = v; }
        else s += __expf(v - mx);
    }
    g_pmax[blockIdx.x * Mc + t] = mx;
    g_psum[blockIdx.x * Mc + t] = s;
}

__global__ void __launch_bounds__(512) k3b() {
    int t = threadIdx.x;
    float mx = g_pmax[t], s = g_psum[t];
    for (int i = 1; i < 256; i++) {
        float m2 = g_pmax[i * Mc + t], s2 = g_psum[i * Mc + t];
        if (m2 > mx) { s = s * __expf(mx - m2) + s2; mx = m2; }
        else s += s2 * __expf(m2 - mx);
    }
    g_colmax[t] = mx;
    g_colinv[t] = 1.0f / s;
}

// ---------------------------------------------------------------------------
// K4: warp per row. Row softmax -> s_memory; s_query in place; top2; wgt;
//     triplet distances; segment-sum atomics.
// grid 8192 x 256 threads (8 warps)
// ---------------------------------------------------------------------------
__global__ void __launch_bounds__(256) k4(float* __restrict__ sq,
                                          float* __restrict__ sm,
                                          const float* __restrict__ keys) {
    const int warp = threadIdx.x >> 5, lane = threadIdx.x & 31;
    const int r = blockIdx.x * 8 + warp;
    const size_t rb = (size_t)r * Mc;

    float v[16];
    #pragma unroll
    for (int k = 0; k < 16; k++) v[k] = sq[rb + lane + (k << 5)];

    // top-2 (value, index), ties -> lower index
    float v1 = -CUDART_INF_F, v2 = -CUDART_INF_F;
    int i1 = 1 << 30, i2 = 1 << 30;
    #pragma unroll
    for (int k = 0; k < 16; k++) {
        float x = v[k]; int idx = lane + (k << 5);
        if (x > v1) { v2 = v1; i2 = i1; v1 = x; i1 = idx; }
        else if (x > v2) { v2 = x; i2 = idx; }
    }
    #pragma unroll
    for (int off = 16; off; off >>= 1) {
        float ov1 = __shfl_down_sync(0xffffffffu, v1, off);
        int   oi1 = __shfl_down_sync(0xffffffffu, i1, off);
        float ov2 = __shfl_down_sync(0xffffffffu, v2, off);
        int   oi2 = __shfl_down_sync(0xffffffffu, i2, off);
        bool og = (ov1 > v1) || (ov1 == v1 && oi1 < i1);
        float w1 = og ? ov1 : v1; int wi1 = og ? oi1 : i1;
        float l1 = og ? v1 : ov1; int li1 = og ? i1 : oi1;
        float ws = og ? ov2 : v2; int wsi = og ? oi2 : i2;
        bool lg = (l1 > ws) || (l1 == ws && li1 < wsi);
        v1 = w1; i1 = wi1;
        v2 = lg ? l1 : ws; i2 = lg ? li1 : wsi;
    }
    v1 = __shfl_sync(0xffffffffu, v1, 0); i1 = __shfl_sync(0xffffffffu, i1, 0);
    i2 = __shfl_sync(0xffffffffu, i2, 0);

    // row softmax
    float es[16], rs = 0.0f;
    #pragma unroll
    for (int k = 0; k < 16; k++) { es[k] = __expf(v[k] - v1); rs += es[k]; }
    #pragma unroll
    for (int off = 16; off; off >>= 1) rs += __shfl_xor_sync(0xffffffffu, rs, off);
    float rinv = 1.0f / rs;

    #pragma unroll
    for (int k = 0; k < 16; k++) {
        int m = lane + (k << 5);
        sm[rb + m] = es[k] * rinv;                                // s_memory
        sq[rb + m] = __expf(v[k] - g_colmax[m]) * g_colinv[m];    // s_query (in place)
    }

    // wgt = (s_query/col_max)[r, top1] = exp(score - colmax)
    float wgt = __expf(v1 - g_colmax[i1]);

    // distances + segment-sum scatter
    float ac = 0.0f, ap = 0.0f, an = 0.0f;
    const float* kp = keys + (size_t)i1 * Dc;
    const float* kn = keys + (size_t)i2 * Dc;
    #pragma unroll
    for (int k = 0; k < 16; k++) {
        int d = lane + (k << 5);
        float qv = g_qr[(size_t)r * Dc + d];
        float pv = kp[d], nv = kn[d];
        float d0 = qv - pv;            ac += d0 * d0;
        float dp = d0 + 1e-6f;         ap += dp * dp;
        float dn = qv - nv + 1e-6f;    an += dn * dn;
        atomicAdd(&g_qupd[i1 * Dc + d], wgt * qv);
    }
    #pragma unroll
    for (int off = 16; off; off >>= 1) {
        ac += __shfl_down_sync(0xffffffffu, ac, off);
        ap += __shfl_down_sync(0xffffffffu, ap, off);
        an += __shfl_down_sync(0xffffffffu, an, off);
    }
    __shared__ float scmp[8], ssep[8];
    if (lane == 0) {
        scmp[warp] = ac;
        ssep[warp] = fmaxf(sqrtf(ap) - sqrtf(an) + 1.0f, 0.0f);
    }
    __syncthreads();
    if (threadIdx.x == 0) {
        float c = 0.0f, s = 0.0f;
        #pragma unroll
        for (int i = 0; i < 8; i++) { c += scmp[i]; s += ssep[i]; }
        atomicAdd(&g_scal[0], c);
        atomicAdd(&g_scal[1], s);
    }
}

// ---------------------------------------------------------------------------
// K7: upd_mem = l2norm(q_update + keys). 512 blocks x 128 threads.
// ---------------------------------------------------------------------------
__global__ void __launch_bounds__(128) k7(const float* __restrict__ keys,
                                          float* __restrict__ updmem) {
    int m = blockIdx.x, t = threadIdx.x;
    float vv[4], ss = 0.0f;
    #pragma unroll
    for (int i = 0; i < 4; i++) {
        int d = t + i * 128;
        vv[i] = g_qupd[m * Dc + d] + keys[m * Dc + d];
        ss += vv[i] * vv[i];
    }
    #pragma unroll
    for (int off = 16; off; off >>= 1) ss += __shfl_xor_sync(0xffffffffu, ss, off);
    __shared__ float sw[4];
    if ((t & 31) == 0) sw[t >> 5] = ss;
    __syncthreads();
    float tot = sw[0] + sw[1] + sw[2] + sw[3];
    float inv = 1.0f / fmaxf(sqrtf(tot), 1e-12f);
    #pragma unroll
    for (int i = 0; i < 4; i++) updmem[m * Dc + t + i * 128] = vv[i] * inv;
}

__global__ void k8(float* __restrict__ o_sep, float* __restrict__ o_comp) {
    *o_sep = g_scal[1] / (float)Nc;
    *o_comp = g_scal[0] / ((float)Nc * (float)Dc);
}

// ---------------------------------------------------------------------------
extern "C" void kernel_launch(void* const* d_in, const int* in_sizes, int n_in,
                              void* d_out, int out_size) {
    const float* query = (const float*)d_in[0];
    const float* keys  = (const float*)d_in[1];
    float* out = (float*)d_out;
    float* o_updq   = out + OFF_UPDQ;
    float* o_updmem = out + OFF_UPDMEM;
    float* o_sq     = out + OFF_SQ;
    float* o_sm     = out + OFF_SM;
    float* o_sep    = out + OFF_SEP;
    float* o_comp   = out + OFF_COMP;

    // CRITICAL FIX: __device__ globals must be resolved to DEVICE addresses
    // before being passed as kernel arguments. Referencing the symbol in host
    // code yields the host-side shadow (readable via ATS on GB300 -> silent
    // zeros, which zeroed the score and concat_mem halves last round).
    float* p_qr = nullptr;
    float* p_keysT = nullptr;
    cudaGetSymbolAddress((void**)&p_qr, g_qr);
    cudaGetSymbolAddress((void**)&p_keysT, g_keysT);

    kz<<<(Mc * Dc + 255) / 256, 256>>>();
    k1_norm<<<Bc * Hc, 256>>>(query, o_updq);
    ktr<<<dim3(16, 16), dim3(32, 8)>>>(keys);

    // score = qr @ keys^T  -> raw scores into s_query region
    sgemm_nt<0><<<dim3(Mc / 128, Nc / 128), 256>>>(p_qr, keys, o_sq);

    k3a<<<256, 512>>>(o_sq);
    k3b<<<1, 512>>>();
    k4<<<Nc / 8, 256>>>(o_sq, o_sm, keys);

    // concat_mem^T = keysT @ s_memory^T -> upd_q second half (coalesced over w)
    sgemm_nt<1><<<dim3(Nc / 128, Dc / 128), 256>>>(p_keysT, o_sm, o_updq);

    k7<<<Mc, 128>>>(keys, o_updmem);
    k8<<<1, 1>>>(o_sep, o_comp);
}

// round 13
// speedup vs baseline: 1.0076x; 1.0074x over previous
#include <cuda_runtime.h>
#include <cuda_bf16.h>
#include <math_constants.h>

// Problem constants
#define Bc 16
#define Dc 512
#define Hc 64
#define Wc 64
#define Mc 512
#define Nc (Bc*Hc*Wc)      // 65536
#define HWc (Hc*Wc)        // 4096

// d_out layout (tuple order: upd_q, upd_mem, s_query, s_memory, separateness, compactness)
#define OFF_UPDQ   0
#define SZ_UPDQ    (Bc*2*Dc*Hc*Wc)        // 67108864
#define OFF_UPDMEM (OFF_UPDQ + SZ_UPDQ)   // 67108864
#define SZ_UPDMEM  (Mc*Dc)                // 262144
#define OFF_SQ     (OFF_UPDMEM + SZ_UPDMEM) // 67371008
#define SZ_SQ      (Nc*Mc)                // 33554432
#define OFF_SM     (OFF_SQ + SZ_SQ)       // 100925440
#define OFF_SEP    (OFF_SM + SZ_SQ)       // 134479872
#define OFF_COMP   (OFF_SEP + 1)          // 134479873

// Scratch (device globals; no allocation in kernel_launch)
__device__ float g_qr[(size_t)Nc * Dc];        // 134 MB: normalized queries, row-major [N, D]
__device__ float g_keysT[Mc * Dc];             // keys transposed [D, M]
__device__ float g_qupd[Mc * Dc];              // segment-sum accumulator
__device__ float g_pmax[256 * Mc];             // column partial max
__device__ float g_psum[256 * Mc];             // column partial sumexp
__device__ float g_colmax[Mc];
__device__ float g_colinv[Mc];                 // 1/colsum
__device__ float g_scal[2];                    // [0]=compactness sum, [1]=separateness sum

// ---------------------------------------------------------------------------
// K0: zero accumulators (must run every launch — graph replays)
// ---------------------------------------------------------------------------
__global__ void kz() {
    int i = blockIdx.x * 256 + threadIdx.x;
    if (i < Mc * Dc) g_qupd[i] = 0.0f;
    if (i < 2) g_scal[i] = 0.0f;
}

// ---------------------------------------------------------------------------
// K1: per-pixel L2 normalize; write qr [N,D] (coalesced via smem transpose)
//     and upd_q first half (same layout as input query).
// grid 1024 (= b*64+h), 256 threads
// ---------------------------------------------------------------------------
__global__ void __launch_bounds__(256) k1_norm(const float* __restrict__ q,
                                               float* __restrict__ updq) {
    __shared__ float tile[128][65];
    __shared__ float ps[4][64];
    __shared__ float sinv[64];
    int bh = blockIdx.x;
    int b = bh >> 6, h = bh & 63;
    int t = threadIdx.x;
    int w = t & 63, seg = t >> 6;

    const float* qp = q + (size_t)b * (Dc * HWc) + h * Wc + w;
    float acc = 0.0f;
    #pragma unroll 4
    for (int d = seg * 128; d < seg * 128 + 128; d++) {
        float x = qp[(size_t)d * HWc];
        acc += x * x;
    }
    ps[seg][w] = acc;
    __syncthreads();
    if (t < 64) {
        float ss = ps[0][t] + ps[1][t] + ps[2][t] + ps[3][t];
        sinv[t] = 1.0f / fmaxf(sqrtf(ss), 1e-12f);
    }
    __syncthreads();

    size_t qbase = (size_t)b * (Dc * HWc) + h * Wc;
    size_t ubase = (size_t)b * (2 * Dc * HWc) + h * Wc;
    size_t rbase = (size_t)bh * 64;
    for (int dc = 0; dc < 4; dc++) {
        for (int i = t; i < 8192; i += 256) {
            int d = i >> 6, ww = i & 63;
            float x = q[qbase + (size_t)(dc * 128 + d) * HWc + ww];
            tile[d][ww] = x;
            updq[ubase + (size_t)(dc * 128 + d) * HWc + ww] = x * sinv[ww];
        }
        __syncthreads();
        for (int i = t; i < 8192; i += 256) {
            int ww = i >> 7, d = i & 127;
            g_qr[(rbase + ww) * Dc + dc * 128 + d] = tile[d][ww] * sinv[ww];
        }
        __syncthreads();
    }
}

// ---------------------------------------------------------------------------
// K_tr: keysT[d][m] = keys[m][d]
// ---------------------------------------------------------------------------
__global__ void ktr(const float* __restrict__ keys) {
    __shared__ float tl[32][33];
    int x = blockIdx.x * 32 + threadIdx.x;   // d
    int y0 = blockIdx.y * 32;                // m
    for (int i = threadIdx.y; i < 32; i += 8)
        tl[i][threadIdx.x] = keys[(y0 + i) * Dc + x];
    __syncthreads();
    int xo = blockIdx.y * 32 + threadIdx.x;  // m
    int yo = blockIdx.x * 32;                // d
    for (int i = threadIdx.y; i < 32; i += 8)
        g_keysT[(yo + i) * Mc + xo] = tl[threadIdx.x][i];
}

// ---------------------------------------------------------------------------
// SGEMM NT: C[row,col] = sum_k A[row,k]*Bm[col,k], K=512 fixed.
// 128x128 tile, BK=16, 256 threads, 8x8 per-thread (4+4 split).
// EPI=0: C -> out[row*512+col]   (score into s_query region)
// EPI=1: row=d, col=r -> upd_q second half [b, 512+d, h, w]
// ---------------------------------------------------------------------------
#define BK 16
#define SSTRIDE 132   // 128+4, keeps 16B alignment for float4 smem loads

template <int EPI>
__global__ void __launch_bounds__(256) sgemm_nt(const float* __restrict__ A,
                                                const float* __restrict__ Bm,
                                                float* __restrict__ out) {
    __shared__ float As[BK][SSTRIDE];
    __shared__ float Bs[BK][SSTRIDE];
    const int tid = threadIdx.x;
    const int tx = tid & 15, ty = tid >> 4;
    const int arow0 = blockIdx.y * 128;
    const int brow0 = blockIdx.x * 128;
    const int lr = tid >> 2;            // 0..63
    const int lk = (tid & 3) * 4;       // 0,4,8,12

    float acc[8][8];
    #pragma unroll
    for (int i = 0; i < 8; i++)
        #pragma unroll
        for (int j = 0; j < 8; j++) acc[i][j] = 0.0f;

    for (int kt = 0; kt < 512; kt += BK) {
        float4 a0 = *(const float4*)&A[(size_t)(arow0 + lr) * 512 + kt + lk];
        float4 a1 = *(const float4*)&A[(size_t)(arow0 + lr + 64) * 512 + kt + lk];
        float4 b0 = *(const float4*)&Bm[(size_t)(brow0 + lr) * 512 + kt + lk];
        float4 b1 = *(const float4*)&Bm[(size_t)(brow0 + lr + 64) * 512 + kt + lk];
        __syncthreads();
        As[lk + 0][lr] = a0.x; As[lk + 1][lr] = a0.y; As[lk + 2][lr] = a0.z; As[lk + 3][lr] = a0.w;
        As[lk + 0][lr + 64] = a1.x; As[lk + 1][lr + 64] = a1.y; As[lk + 2][lr + 64] = a1.z; As[lk + 3][lr + 64] = a1.w;
        Bs[lk + 0][lr] = b0.x; Bs[lk + 1][lr] = b0.y; Bs[lk + 2][lr] = b0.z; Bs[lk + 3][lr] = b0.w;
        Bs[lk + 0][lr + 64] = b1.x; Bs[lk + 1][lr + 64] = b1.y; Bs[lk + 2][lr + 64] = b1.z; Bs[lk + 3][lr + 64] = b1.w;
        __syncthreads();
        #pragma unroll
        for (int kk = 0; kk < BK; kk++) {
            float4 ra0 = *(const float4*)&As[kk][ty * 4];
            float4 ra1 = *(const float4*)&As[kk][64 + ty * 4];
            float4 rb0 = *(const float4*)&Bs[kk][tx * 4];
            float4 rb1 = *(const float4*)&Bs[kk][64 + tx * 4];
            float a[8] = {ra0.x, ra0.y, ra0.z, ra0.w, ra1.x, ra1.y, ra1.z, ra1.w};
            float bb[8] = {rb0.x, rb0.y, rb0.z, rb0.w, rb1.x, rb1.y, rb1.z, rb1.w};
            #pragma unroll
            for (int i = 0; i < 8; i++)
                #pragma unroll
                for (int j = 0; j < 8; j++) acc[i][j] += a[i] * bb[j];
        }
    }

    #pragma unroll
    for (int hi = 0; hi < 2; hi++) {
        #pragma unroll
        for (int i = 0; i < 4; i++) {
            int row = arow0 + hi * 64 + ty * 4 + i;
            #pragma unroll
            for (int hj = 0; hj < 2; hj++) {
                int col = brow0 + hj * 64 + tx * 4;
                float4 v;
                v.x = acc[hi * 4 + i][hj * 4 + 0];
                v.y = acc[hi * 4 + i][hj * 4 + 1];
                v.z = acc[hi * 4 + i][hj * 4 + 2];
                v.w = acc[hi * 4 + i][hj * 4 + 3];
                if (EPI == 0) {
                    *(float4*)&out[(size_t)row * 512 + col] = v;
                } else {
                    // row = d, col = r = (b*64+h)*64 + w ; w%4==0 so float4 safe
                    int r = col;
                    int bb2 = r >> 12, hh = (r >> 6) & 63, ww = r & 63;
                    size_t idx = (size_t)bb2 * (2 * Dc * HWc) + (size_t)(Dc + row) * HWc + hh * Wc + ww;
                    *(float4*)&out[idx] = v;
                }
            }
        }
    }
}

// ---------------------------------------------------------------------------
// K3a: per-block online column (max, sumexp) over 256 rows. 256 blocks x 512 thr.
// ---------------------------------------------------------------------------
__global__ void __launch_bounds__(512) k3a(const float* __restrict__ raw) {
    int t = threadIdx.x;
    const float* p = raw + (size_t)blockIdx.x * 256 * Mc + t;
    float mx = -CUDART_INF_F, s = 0.0f;
    for (int n = 0; n < 256; n++) {
        float v = p[(size_t)n * Mc];
        if (v > mx) { s = s * __expf(mx - v) + 1.0f; mx = v; }
        else s += __expf(v - mx);
    }
    g_pmax[blockIdx.x * Mc + t] = mx;
    g_psum[blockIdx.x * Mc + t] = s;
}

__global__ void __launch_bounds__(512) k3b() {
    int t = threadIdx.x;
    float mx = g_pmax[t], s = g_psum[t];
    for (int i = 1; i < 256; i++) {
        float m2 = g_pmax[i * Mc + t], s2 = g_psum[i * Mc + t];
        if (m2 > mx) { s = s * __expf(mx - m2) + s2; mx = m2; }
        else s += s2 * __expf(m2 - mx);
    }
    g_colmax[t] = mx;
    g_colinv[t] = 1.0f / s;
}

// ---------------------------------------------------------------------------
// K4: warp per row. Row softmax -> s_memory; s_query in place; top2; wgt;
//     triplet distances; segment-sum atomics.
// grid 8192 x 256 threads (8 warps)
// ---------------------------------------------------------------------------
__global__ void __launch_bounds__(256) k4(float* __restrict__ sq,
                                          float* __restrict__ sm,
                                          const float* __restrict__ keys) {
    const int warp = threadIdx.x >> 5, lane = threadIdx.x & 31;
    const int r = blockIdx.x * 8 + warp;
    const size_t rb = (size_t)r * Mc;

    float v[16];
    #pragma unroll
    for (int k = 0; k < 16; k++) v[k] = sq[rb + lane + (k << 5)];

    // top-2 (value, index), ties -> lower index
    float v1 = -CUDART_INF_F, v2 = -CUDART_INF_F;
    int i1 = 1 << 30, i2 = 1 << 30;
    #pragma unroll
    for (int k = 0; k < 16; k++) {
        float x = v[k]; int idx = lane + (k << 5);
        if (x > v1) { v2 = v1; i2 = i1; v1 = x; i1 = idx; }
        else if (x > v2) { v2 = x; i2 = idx; }
    }
    #pragma unroll
    for (int off = 16; off; off >>= 1) {
        float ov1 = __shfl_down_sync(0xffffffffu, v1, off);
        int   oi1 = __shfl_down_sync(0xffffffffu, i1, off);
        float ov2 = __shfl_down_sync(0xffffffffu, v2, off);
        int   oi2 = __shfl_down_sync(0xffffffffu, i2, off);
        bool og = (ov1 > v1) || (ov1 == v1 && oi1 < i1);
        float w1 = og ? ov1 : v1; int wi1 = og ? oi1 : i1;
        float l1 = og ? v1 : ov1; int li1 = og ? i1 : oi1;
        float ws = og ? ov2 : v2; int wsi = og ? oi2 : i2;
        bool lg = (l1 > ws) || (l1 == ws && li1 < wsi);
        v1 = w1; i1 = wi1;
        v2 = lg ? l1 : ws; i2 = lg ? li1 : wsi;
    }
    v1 = __shfl_sync(0xffffffffu, v1, 0); i1 = __shfl_sync(0xffffffffu, i1, 0);
    i2 = __shfl_sync(0xffffffffu, i2, 0);

    // row softmax
    float es[16], rs = 0.0f;
    #pragma unroll
    for (int k = 0; k < 16; k++) { es[k] = __expf(v[k] - v1); rs += es[k]; }
    #pragma unroll
    for (int off = 16; off; off >>= 1) rs += __shfl_xor_sync(0xffffffffu, rs, off);
    float rinv = 1.0f / rs;

    #pragma unroll
    for (int k = 0; k < 16; k++) {
        int m = lane + (k << 5);
        sm[rb + m] = es[k] * rinv;                                // s_memory
        sq[rb + m] = __expf(v[k] - g_colmax[m]) * g_colinv[m];    // s_query (in place)
    }

    // wgt = (s_query/col_max)[r, top1] = exp(score - colmax)
    float wgt = __expf(v1 - g_colmax[i1]);

    // distances + segment-sum scatter
    float ac = 0.0f, ap = 0.0f, an = 0.0f;
    const float* kp = keys + (size_t)i1 * Dc;
    const float* kn = keys + (size_t)i2 * Dc;
    #pragma unroll
    for (int k = 0; k < 16; k++) {
        int d = lane + (k << 5);
        float qv = g_qr[(size_t)r * Dc + d];
        float pv = kp[d], nv = kn[d];
        float d0 = qv - pv;            ac += d0 * d0;
        float dp = d0 + 1e-6f;         ap += dp * dp;
        float dn = qv - nv + 1e-6f;    an += dn * dn;
        atomicAdd(&g_qupd[i1 * Dc + d], wgt * qv);
    }
    #pragma unroll
    for (int off = 16; off; off >>= 1) {
        ac += __shfl_down_sync(0xffffffffu, ac, off);
        ap += __shfl_down_sync(0xffffffffu, ap, off);
        an += __shfl_down_sync(0xffffffffu, an, off);
    }
    __shared__ float scmp[8], ssep[8];
    if (lane == 0) {
        scmp[warp] = ac;
        ssep[warp] = fmaxf(sqrtf(ap) - sqrtf(an) + 1.0f, 0.0f);
    }
    __syncthreads();
    if (threadIdx.x == 0) {
        float c = 0.0f, s = 0.0f;
        #pragma unroll
        for (int i = 0; i < 8; i++) { c += scmp[i]; s += ssep[i]; }
        atomicAdd(&g_scal[0], c);
        atomicAdd(&g_scal[1], s);
    }
}

// ---------------------------------------------------------------------------
// K7: upd_mem = l2norm(q_update + keys). 512 blocks x 128 threads.
// ---------------------------------------------------------------------------
__global__ void __launch_bounds__(128) k7(const float* __restrict__ keys,
                                          float* __restrict__ updmem) {
    int m = blockIdx.x, t = threadIdx.x;
    float vv[4], ss = 0.0f;
    #pragma unroll
    for (int i = 0; i < 4; i++) {
        int d = t + i * 128;
        vv[i] = g_qupd[m * Dc + d] + keys[m * Dc + d];
        ss += vv[i] * vv[i];
    }
    #pragma unroll
    for (int off = 16; off; off >>= 1) ss += __shfl_xor_sync(0xffffffffu, ss, off);
    __shared__ float sw[4];
    if ((t & 31) == 0) sw[t >> 5] = ss;
    __syncthreads();
    float tot = sw[0] + sw[1] + sw[2] + sw[3];
    float inv = 1.0f / fmaxf(sqrtf(tot), 1e-12f);
    #pragma unroll
    for (int i = 0; i < 4; i++) updmem[m * Dc + t + i * 128] = vv[i] * inv;
}

__global__ void k8(float* __restrict__ o_sep, float* __restrict__ o_comp) {
    *o_sep = g_scal[1] / (float)Nc;
    *o_comp = g_scal[0] / ((float)Nc * (float)Dc);
}

// ---------------------------------------------------------------------------
extern "C" void kernel_launch(void* const* d_in, const int* in_sizes, int n_in,
                              void* d_out, int out_size) {
    const float* query = (const float*)d_in[0];
    const float* keys  = (const float*)d_in[1];
    float* out = (float*)d_out;
    float* o_updq   = out + OFF_UPDQ;
    float* o_updmem = out + OFF_UPDMEM;
    float* o_sq     = out + OFF_SQ;
    float* o_sm     = out + OFF_SM;
    float* o_sep    = out + OFF_SEP;
    float* o_comp   = out + OFF_COMP;

    // CRITICAL FIX: __device__ globals must be resolved to DEVICE addresses
    // before being passed as kernel arguments. Referencing the symbol in host
    // code yields the host-side shadow (readable via ATS on GB300 -> silent
    // zeros, which zeroed the score and concat_mem halves last round).
    float* p_qr = nullptr;
    float* p_keysT = nullptr;
    cudaGetSymbolAddress((void**)&p_qr, g_qr);
    cudaGetSymbolAddress((void**)&p_keysT, g_keysT);

    kz<<<(Mc * Dc + 255) / 256, 256>>>();
    k1_norm<<<Bc * Hc, 256>>>(query, o_updq);
    ktr<<<dim3(16, 16), dim3(32, 8)>>>(keys);

    // score = qr @ keys^T  -> raw scores into s_query region
    sgemm_nt<0><<<dim3(Mc / 128, Nc / 128), 256>>>(p_qr, keys, o_sq);

    k3a<<<256, 512>>>(o_sq);
    k3b<<<1, 512>>>();
    k4<<<Nc / 8, 256>>>(o_sq, o_sm, keys);

    // concat_mem^T = keysT @ s_memory^T -> upd_q second half (coalesced over w)
    sgemm_nt<1><<<dim3(Nc / 128, Dc / 128), 256>>>(p_keysT, o_sm, o_updq);

    k7<<<Mc, 128>>>(keys, o_updmem);
    k8<<<1, 1>>>(o_sep, o_comp);
}